// round 3
// baseline (speedup 1.0000x reference)
#include <cuda_runtime.h>
#include <math.h>

// ---------------- problem constants ----------------
#define Bb   4
#define Tt   168
#define Nn   16
#define Ff   16
#define BT   (Bb*Tt)          // 672
#define Dd   4096
#define HDp  512
#define DFF  16384
#define NF   256              // N*F
#define BTD  (BT*Dd)          // 2752512
#define HH   4                // heads (TOPK)
#define HDIM 1024             // D/H
#define WINC 25
#define PADC 12

// ---------------- scratch (device globals; no allocs) ----------------
__device__ float g_MG[BTD];
__device__ float g_Y[BTD];
__device__ float g_hid[BT*Nn*HDp];
__device__ float g_os[BT*Nn*Nn];
__device__ float g_ds[BT*Nn*Nn];
__device__ float g_x[BTD];
__device__ float g_xn[BTD];
__device__ float g_q[BTD];
__device__ float g_k[BTD];
__device__ float g_v[BTD];
__device__ float g_ao[BTD];
__device__ float g_ffn[BT*DFF];
__device__ float g_xm[BT];
__device__ int   g_per[Bb*HH];
__device__ float g_To[3*Nn*Nn];
__device__ float g_Td[3*Nn*Nn];

// ---------------- Chebyshev basis: {I, L, 2L^2 - I} ----------------
__global__ void basis_kernel(const float* __restrict__ Lo, const float* __restrict__ Ld)
{
    int tid = threadIdx.x;            // 256 threads -> (i,j)
    int i = tid >> 4, j = tid & 15;
    float eye = (i == j) ? 1.f : 0.f;
    float so = 0.f, sd = 0.f;
    #pragma unroll
    for (int k = 0; k < 16; k++) {
        so = fmaf(Lo[i*16+k], Lo[k*16+j], so);
        sd = fmaf(Ld[i*16+k], Ld[k*16+j], sd);
    }
    g_To[0*256+tid] = eye;
    g_To[1*256+tid] = Lo[tid];
    g_To[2*256+tid] = 2.f*so - eye;
    g_Td[0*256+tid] = eye;
    g_Td[1*256+tid] = Ld[tid];
    g_Td[2*256+tid] = 2.f*sd - eye;
}

// ---------------- TwoDGCN ----------------
__global__ __launch_bounds__(256) void gcn_kernel(const float* __restrict__ M,
                                                  const float* __restrict__ theta)
{
    int bt = blockIdx.x;
    __shared__ float Msm[16][16][16];   // (j,k,f)
    __shared__ float tmp[16][16][16];   // (i,k,f)
    __shared__ float th[3][3][16][16];
    __shared__ float Tos[3][16][16];
    __shared__ float Tds[3][16][16];
    int tid = threadIdx.x;
    const float* Mb = M + (size_t)bt * 4096;
    for (int idx = tid; idx < 4096; idx += 256) ((float*)Msm)[idx] = Mb[idx];
    for (int idx = tid; idx < 2304; idx += 256) ((float*)th)[idx]  = theta[idx];
    for (int idx = tid; idx < 768;  idx += 256) {
        ((float*)Tos)[idx] = g_To[idx];
        ((float*)Tds)[idx] = g_Td[idx];
    }
    int i = tid >> 4, l = tid & 15;
    float acc[16];
    #pragma unroll
    for (int g = 0; g < 16; g++) acc[g] = 0.f;

    for (int a = 0; a < 3; a++) {
        __syncthreads();
        {
            float o[16];
            #pragma unroll
            for (int f = 0; f < 16; f++) o[f] = 0.f;
            #pragma unroll
            for (int j = 0; j < 16; j++) {
                float w = Tos[a][i][j];
                #pragma unroll
                for (int f = 0; f < 16; f++) o[f] = fmaf(w, Msm[j][l][f], o[f]);
            }
            #pragma unroll
            for (int f = 0; f < 16; f++) tmp[i][l][f] = o[f];
        }
        __syncthreads();
        for (int c = 0; c < 3; c++) {
            float P[16];
            #pragma unroll
            for (int f = 0; f < 16; f++) P[f] = 0.f;
            #pragma unroll
            for (int k = 0; k < 16; k++) {
                float w = Tds[c][k][l];
                #pragma unroll
                for (int f = 0; f < 16; f++) P[f] = fmaf(w, tmp[i][k][f], P[f]);
            }
            #pragma unroll
            for (int f = 0; f < 16; f++) {
                float pv = P[f];
                #pragma unroll
                for (int g = 0; g < 16; g++) acc[g] = fmaf(pv, th[a][c][f][g], acc[g]);
            }
        }
    }
    float* out = g_MG + (size_t)bt * 4096 + (i*16 + l) * 16;
    #pragma unroll
    for (int g = 0; g < 16; g++) out[g] = acc[g];
}

// ---------------- destination view: Y[bt,n,k,f] = M[bt,k,n,f] ----------------
__global__ void transY_kernel(const float* __restrict__ M)
{
    int bt = blockIdx.x;
    int tid = threadIdx.x;
    int n = tid >> 4, k = tid & 15;
    const float* src = M   + (((size_t)bt*16 + k)*16 + n)*16;
    float*       dst = g_Y + (((size_t)bt*16 + n)*16 + k)*16;
    #pragma unroll
    for (int f = 0; f < 16; f++) dst[f] = src[f];
}

// ---------------- generic SGEMM: C = act(A@W + bias) + res ----------------
// BM=BN=128, BK=8, 256 threads, 8x8 microtile, double-buffered smem (1 sync/K-step).
__device__ __forceinline__ float gelu_exact(float v)
{
    return 0.5f * v * (1.0f + erff(v * 0.70710678118654752440f));
}

__global__ __launch_bounds__(256) void sgemm_kernel(
    const float* __restrict__ A, const float* __restrict__ W,
    const float* __restrict__ bias, const float* __restrict__ res,
    float* __restrict__ C, int M, int N, int K, int act)
{
    __shared__ float As[2][8][128];
    __shared__ float Bs[2][8][128];
    int tid = threadIdx.x;
    int bm = blockIdx.y * 128;
    int bn = blockIdx.x * 128;
    int ar = tid >> 1;               // A tile row 0..127
    int ac = (tid & 1) << 2;         // A tile col {0,4}
    int br = tid >> 5;               // B tile row 0..7
    int bc = (tid & 31) << 2;        // B tile col 0..124
    int tr = (tid >> 4) << 3;        // out row base
    int tc = (tid & 15) << 3;        // out col base

    int arow = bm + ar;
    bool aval = arow < M;
    const float* Aptr = A + (size_t)arow * K + ac;
    const float* Bptr = W + (size_t)br * N + bn + bc;

    float acc[8][8];
    #pragma unroll
    for (int i = 0; i < 8; i++)
        #pragma unroll
        for (int j = 0; j < 8; j++) acc[i][j] = 0.f;

    // preload tile 0 into buffer 0
    {
        float4 av = aval ? *(const float4*)(Aptr) : make_float4(0,0,0,0);
        float4 bv = *(const float4*)(Bptr);
        As[0][ac+0][ar] = av.x; As[0][ac+1][ar] = av.y;
        As[0][ac+2][ar] = av.z; As[0][ac+3][ar] = av.w;
        *(float4*)&Bs[0][br][bc] = bv;
    }
    __syncthreads();

    int nk = K >> 3;
    for (int kt = 0; kt < nk; kt++) {
        int cur = kt & 1;
        bool has_next = (kt + 1) < nk;
        float4 av, bv;
        if (has_next) {
            int koff = (kt + 1) << 3;
            av = aval ? *(const float4*)(Aptr + koff) : make_float4(0,0,0,0);
            bv = *(const float4*)(Bptr + (size_t)koff * N);
        }
        #pragma unroll
        for (int kk = 0; kk < 8; kk++) {
            float af[8], bf[8];
            #pragma unroll
            for (int u = 0; u < 8; u++) af[u] = As[cur][kk][tr+u];
            #pragma unroll
            for (int u = 0; u < 8; u++) bf[u] = Bs[cur][kk][tc+u];
            #pragma unroll
            for (int i = 0; i < 8; i++)
                #pragma unroll
                for (int j = 0; j < 8; j++)
                    acc[i][j] = fmaf(af[i], bf[j], acc[i][j]);
        }
        if (has_next) {
            int nxt = cur ^ 1;
            As[nxt][ac+0][ar] = av.x; As[nxt][ac+1][ar] = av.y;
            As[nxt][ac+2][ar] = av.z; As[nxt][ac+3][ar] = av.w;
            *(float4*)&Bs[nxt][br][bc] = bv;
            __syncthreads();
        }
    }

    #pragma unroll
    for (int i = 0; i < 8; i++) {
        int row = bm + tr + i;
        if (row < M) {
            size_t base = (size_t)row * N + bn + tc;
            #pragma unroll
            for (int j = 0; j < 8; j++) {
                float v = acc[i][j];
                if (bias) v += bias[bn + tc + j];
                if (act == 1) v = gelu_exact(v);
                if (res) v += res[base + j];
                C[base + j] = v;
            }
        }
    }
}

// ---------------- fused QKV over blockIdx.z (double-buffered) ----------------
__global__ __launch_bounds__(256) void qkv_kernel(
    const float* __restrict__ A,
    const float* __restrict__ Wq, const float* __restrict__ bq,
    const float* __restrict__ Wk, const float* __restrict__ bk,
    const float* __restrict__ Wv, const float* __restrict__ bv)
{
    const float* W; const float* bias; float* C;
    if (blockIdx.z == 0)      { W = Wq; bias = bq; C = g_q; }
    else if (blockIdx.z == 1) { W = Wk; bias = bk; C = g_k; }
    else                      { W = Wv; bias = bv; C = g_v; }

    __shared__ float As[2][8][128];
    __shared__ float Bs[2][8][128];
    int tid = threadIdx.x;
    int bm = blockIdx.y * 128;
    int bn = blockIdx.x * 128;
    int ar = tid >> 1;
    int ac = (tid & 1) << 2;
    int br = tid >> 5;
    int bc = (tid & 31) << 2;
    int tr = (tid >> 4) << 3;
    int tc = (tid & 15) << 3;

    int arow = bm + ar;
    bool aval = arow < BT;
    const float* Aptr = A + (size_t)arow * Dd + ac;
    const float* Bptr = W + (size_t)br * Dd + bn + bc;

    float acc[8][8];
    #pragma unroll
    for (int i = 0; i < 8; i++)
        #pragma unroll
        for (int j = 0; j < 8; j++) acc[i][j] = 0.f;

    {
        float4 av = aval ? *(const float4*)(Aptr) : make_float4(0,0,0,0);
        float4 bv4 = *(const float4*)(Bptr);
        As[0][ac+0][ar] = av.x; As[0][ac+1][ar] = av.y;
        As[0][ac+2][ar] = av.z; As[0][ac+3][ar] = av.w;
        *(float4*)&Bs[0][br][bc] = bv4;
    }
    __syncthreads();

    const int nk = Dd >> 3;
    for (int kt = 0; kt < nk; kt++) {
        int cur = kt & 1;
        bool has_next = (kt + 1) < nk;
        float4 av, bv4;
        if (has_next) {
            int koff = (kt + 1) << 3;
            av  = aval ? *(const float4*)(Aptr + koff) : make_float4(0,0,0,0);
            bv4 = *(const float4*)(Bptr + (size_t)koff * Dd);
        }
        #pragma unroll
        for (int kk = 0; kk < 8; kk++) {
            float af[8], bf[8];
            #pragma unroll
            for (int u = 0; u < 8; u++) af[u] = As[cur][kk][tr+u];
            #pragma unroll
            for (int u = 0; u < 8; u++) bf[u] = Bs[cur][kk][tc+u];
            #pragma unroll
            for (int i = 0; i < 8; i++)
                #pragma unroll
                for (int j = 0; j < 8; j++)
                    acc[i][j] = fmaf(af[i], bf[j], acc[i][j]);
        }
        if (has_next) {
            int nxt = cur ^ 1;
            As[nxt][ac+0][ar] = av.x; As[nxt][ac+1][ar] = av.y;
            As[nxt][ac+2][ar] = av.z; As[nxt][ac+3][ar] = av.w;
            *(float4*)&Bs[nxt][br][bc] = bv4;
            __syncthreads();
        }
    }

    #pragma unroll
    for (int i = 0; i < 8; i++) {
        int row = bm + tr + i;
        if (row < BT) {
            size_t base = (size_t)row * Dd + bn + tc;
            #pragma unroll
            for (int j = 0; j < 8; j++)
                C[base + j] = acc[i][j] + bias[bn + tc + j];
        }
    }
}

// ---------------- small GEMM: (Mrows x 512)@(512 x 16) + bias ----------------
__global__ void gemm_n16_kernel(const float* __restrict__ A, const float* __restrict__ W,
                                const float* __restrict__ bias, float* __restrict__ C, int Mrows)
{
    int g = blockIdx.x * blockDim.x + threadIdx.x;
    if (g >= Mrows * 16) return;
    int row = g >> 4, o = g & 15;
    const float* a = A + (size_t)row * 512;
    float s = 0.f;
    for (int k = 0; k < 512; k++) s = fmaf(a[k], W[k*16 + o], s);
    C[g] = s + bias[o];
}

// ---------------- entropy-sparse OD mixing + Ms + row means ----------------
__global__ __launch_bounds__(256) void sparse_ms_kernel(const float* __restrict__ M)
{
    int bt = blockIdx.x;
    int tid = threadIdx.x;
    __shared__ float Msm[16][16][16];
    __shared__ float tsm[16][16][16];
    __shared__ float po[16][16], pd[16][16];
    __shared__ float ento[16], entd[16];
    __shared__ int   selo[16], seld[16];
    __shared__ float red[256];

    const float* Mb = M + (size_t)bt * 4096;
    for (int idx = tid; idx < 4096; idx += 256) ((float*)Msm)[idx] = Mb[idx];

    if (tid < 32) {
        int r = tid & 15;
        const float* src = (tid < 16 ? g_os : g_ds) + (size_t)bt*256 + r*16;
        float mx = -1e30f;
        #pragma unroll
        for (int j = 0; j < 16; j++) mx = fmaxf(mx, src[j]);
        float e[16], s = 0.f;
        #pragma unroll
        for (int j = 0; j < 16; j++) { e[j] = expf(src[j] - mx); s += e[j]; }
        float inv = 1.f / s, ent = 0.f;
        #pragma unroll
        for (int j = 0; j < 16; j++) {
            float p = e[j] * inv;
            if (tid < 16) po[r][j] = p; else pd[r][j] = p;
            ent -= p * logf(p + 1e-9f);
        }
        if (tid < 16) ento[r] = ent; else entd[r] = ent;
    }
    __syncthreads();
    if (tid < 2) {
        float* ent = (tid == 0) ? ento : entd;
        int*   sel = (tid == 0) ? selo : seld;
        #pragma unroll
        for (int r = 0; r < 16; r++) sel[r] = 0;
        int i1 = 0; float b1 = 1e30f;
        for (int r = 0; r < 16; r++) if (ent[r] < b1) { b1 = ent[r]; i1 = r; }
        int i2 = 0; float b2 = 1e30f;
        for (int r = 0; r < 16; r++) if (r != i1 && ent[r] < b2) { b2 = ent[r]; i2 = r; }
        sel[i1] = 1; sel[i2] = 1;
    }
    __syncthreads();

    {
        int i = tid >> 4, k = tid & 15;
        float o[16];
        #pragma unroll
        for (int f = 0; f < 16; f++) o[f] = 0.f;
        if (selo[i]) {
            #pragma unroll
            for (int j = 0; j < 16; j++) {
                float w = po[i][j];
                #pragma unroll
                for (int f = 0; f < 16; f++) o[f] = fmaf(w, Msm[j][k][f], o[f]);
            }
        }
        #pragma unroll
        for (int f = 0; f < 16; f++) tsm[i][k][f] = o[f];
    }
    __syncthreads();

    int ii = tid >> 4, jj = tid & 15;
    float dj[16];
    #pragma unroll
    for (int f = 0; f < 16; f++) dj[f] = seld[jj] ? pd[jj][f] : 0.f;
    const float* MGb = g_MG + (size_t)bt * 4096;
    float*       xb  = g_x  + (size_t)bt * 4096;
    float local = 0.f;
    #pragma unroll
    for (int kk = 0; kk < 16; kk++) {
        float ma = 0.f;
        #pragma unroll
        for (int f = 0; f < 16; f++) ma = fmaf(tsm[ii][kk][f], dj[f], ma);
        int idx = (ii*16 + jj)*16 + kk;
        float ms = 0.5f * (MGb[idx] + ma);
        xb[idx] = ms;
        local += ms;
    }
    red[tid] = local;
    __syncthreads();
    for (int off = 128; off > 0; off >>= 1) {
        if (tid < off) red[tid] += red[tid + off];
        __syncthreads();
    }
    if (tid == 0) g_xm[bt] = red[0] / 4096.f;
}

// ---------------- periodicity ----------------
__global__ void period_kernel(float* __restrict__ out_tail, int write_tail)
{
    int b = blockIdx.x;
    int tid = threadIdx.x;
    __shared__ float xs[Tt], det[Tt], xc[Tt], ac[Tt];
    __shared__ float red[256];
    if (tid < Tt) xs[tid] = g_xm[b*Tt + tid];
    __syncthreads();
    if (tid < Tt) {
        float s = 0.f;
        for (int d = -PADC; d <= PADC; d++) {
            int u = tid + d;
            u = u < 0 ? 0 : (u > Tt-1 ? Tt-1 : u);
            s += xs[u];
        }
        det[tid] = xs[tid] - s / (float)WINC;
    }
    __syncthreads();
    red[tid] = (tid < Tt) ? det[tid] : 0.f;
    __syncthreads();
    for (int off = 128; off > 0; off >>= 1) {
        if (tid < off) red[tid] += red[tid + off];
        __syncthreads();
    }
    float mean = red[0] / (float)Tt;
    if (tid < Tt) xc[tid] = det[tid] - mean;
    __syncthreads();
    if (tid < Tt) {
        int k = tid;
        float s = 0.f;
        for (int u = 0; u + k < Tt; u++) s = fmaf(xc[u], xc[u+k], s);
        ac[k] = (k < 2) ? -1e9f : s;
    }
    __syncthreads();
    if (tid == 0) {
        int used[HH];
        for (int r = 0; r < HH; r++) {
            float best = -1e30f; int bi = 0;
            for (int k = 0; k < Tt; k++) {
                bool skip = false;
                for (int q = 0; q < r; q++) if (used[q] == k) skip = true;
                if (!skip && ac[k] > best) { best = ac[k]; bi = k; }
            }
            used[r] = bi;
            g_per[b*HH + r] = bi;
            if (write_tail) out_tail[b*HH + r] = (float)bi;
        }
    }
}

// ---------------- LayerNorm ----------------
__global__ __launch_bounds__(256) void ln_kernel(const float* __restrict__ X,
                                                 const float* __restrict__ gam,
                                                 const float* __restrict__ bet,
                                                 float* __restrict__ Y)
{
    int row = blockIdx.x;
    int tid = threadIdx.x;
    __shared__ float red[256];
    __shared__ float mu_s, rs_s;
    const float* x = X + (size_t)row * Dd;
    float s = 0.f;
    for (int i = tid; i < Dd; i += 256) s += x[i];
    red[tid] = s; __syncthreads();
    for (int off = 128; off > 0; off >>= 1) {
        if (tid < off) red[tid] += red[tid + off];
        __syncthreads();
    }
    if (tid == 0) mu_s = red[0] / (float)Dd;
    __syncthreads();
    float mu = mu_s;
    float s2 = 0.f;
    for (int i = tid; i < Dd; i += 256) { float d = x[i] - mu; s2 = fmaf(d, d, s2); }
    red[tid] = s2; __syncthreads();
    for (int off = 128; off > 0; off >>= 1) {
        if (tid < off) red[tid] += red[tid + off];
        __syncthreads();
    }
    if (tid == 0) rs_s = rsqrtf(red[0] / (float)Dd + 1e-5f);
    __syncthreads();
    float rs = rs_s;
    float* y = Y + (size_t)row * Dd;
    for (int i = tid; i < Dd; i += 256)
        y[i] = (x[i] - mu) * rs * gam[i] + bet[i];
}

// ---------------- period-sparse causal attention ----------------
__global__ __launch_bounds__(256) void attn_kernel()
{
    int blk = blockIdx.x;
    int i = blk % Tt;
    int h = (blk / Tt) & 3;
    int b = blk / (Tt * HH);
    int p = g_per[b*HH + h];
    if (p < 1) p = 1;
    int nj = i / p + 1;

    __shared__ float sc[96];
    __shared__ float sinv;
    int tid = threadIdx.x, lane = tid & 31, w = tid >> 5;

    const float* q = g_q + ((size_t)(b*Tt + i) * Dd) + h*HDIM;
    for (int m = w; m < nj; m += 8) {
        int j = i - m*p;
        const float* kr = g_k + ((size_t)(b*Tt + j) * Dd) + h*HDIM;
        float s = 0.f;
        for (int l = lane; l < HDIM; l += 32) s = fmaf(q[l], kr[l], s);
        #pragma unroll
        for (int off = 16; off; off >>= 1) s += __shfl_xor_sync(0xffffffffu, s, off);
        if (lane == 0) sc[m] = s * (1.f/32.f);
    }
    __syncthreads();
    if (tid == 0) {
        float mx = -1e30f;
        for (int m = 0; m < nj; m++) mx = fmaxf(mx, sc[m]);
        float su = 0.f;
        for (int m = 0; m < nj; m++) { float e = expf(sc[m] - mx); sc[m] = e; su += e; }
        sinv = 1.f / su;
    }
    __syncthreads();
    float inv = sinv;
    float acc[4] = {0.f, 0.f, 0.f, 0.f};
    for (int m = 0; m < nj; m++) {
        int j = i - m*p;
        float a = sc[m] * inv;
        const float* vr = g_v + ((size_t)(b*Tt + j) * Dd) + h*HDIM;
        #pragma unroll
        for (int u = 0; u < 4; u++) acc[u] = fmaf(a, vr[tid + u*256], acc[u]);
    }
    float* o = g_ao + ((size_t)(b*Tt + i) * Dd) + h*HDIM;
    #pragma unroll
    for (int u = 0; u < 4; u++) o[tid + u*256] = acc[u];
}

// ---------------- launch ----------------
extern "C" void kernel_launch(void* const* d_in, const int* in_sizes, int n_in,
                              void* d_out, int out_size)
{
    const float* M     = (const float*)d_in[0];
    const float* L_o   = (const float*)d_in[1];
    const float* L_d   = (const float*)d_in[2];
    const float* theta = (const float*)d_in[3];
    const float* Wop   = (const float*)d_in[4];
    const float* bop   = (const float*)d_in[5];
    const float* Wdp   = (const float*)d_in[6];
    const float* bdp   = (const float*)d_in[7];
    const float* Wos   = (const float*)d_in[8];
    const float* bos   = (const float*)d_in[9];
    const float* Wds   = (const float*)d_in[10];
    const float* bds   = (const float*)d_in[11];
    const float* Wq    = (const float*)d_in[12];
    const float* bq    = (const float*)d_in[13];
    const float* Wk    = (const float*)d_in[14];
    const float* bk    = (const float*)d_in[15];
    const float* Wv    = (const float*)d_in[16];
    const float* bv    = (const float*)d_in[17];
    const float* Wo    = (const float*)d_in[18];
    const float* bo    = (const float*)d_in[19];
    const float* W1    = (const float*)d_in[20];
    const float* b1    = (const float*)d_in[21];
    const float* W2    = (const float*)d_in[22];
    const float* b2    = (const float*)d_in[23];
    const float* g1    = (const float*)d_in[24];
    const float* be1   = (const float*)d_in[25];
    const float* g2    = (const float*)d_in[26];
    const float* be2   = (const float*)d_in[27];

    float *pY, *pHid, *pOs, *pDs, *pX, *pXn, *pAo, *pFfn;
    cudaGetSymbolAddress((void**)&pY,   g_Y);
    cudaGetSymbolAddress((void**)&pHid, g_hid);
    cudaGetSymbolAddress((void**)&pOs,  g_os);
    cudaGetSymbolAddress((void**)&pDs,  g_ds);
    cudaGetSymbolAddress((void**)&pX,   g_x);
    cudaGetSymbolAddress((void**)&pXn,  g_xn);
    cudaGetSymbolAddress((void**)&pAo,  g_ao);
    cudaGetSymbolAddress((void**)&pFfn, g_ffn);

    float* out = (float*)d_out;
    int write_tail = (out_size >= BTD + Bb*HH) ? 1 : 0;

    // 1) GCN branch
    basis_kernel<<<1, 256>>>(L_o, L_d);
    gcn_kernel<<<BT, 256>>>(M, theta);

    // 2) OD attention scores
    transY_kernel<<<BT, 256>>>(M);
    sgemm_kernel<<<dim3(HDp/128, (BT*Nn)/128), 256>>>(M,  Wop, bop, nullptr, pHid, BT*Nn, HDp, NF, 0);
    gemm_n16_kernel<<<(BT*Nn*16 + 255)/256, 256>>>(pHid, Wos, bos, pOs, BT*Nn);
    sgemm_kernel<<<dim3(HDp/128, (BT*Nn)/128), 256>>>(pY, Wdp, bdp, nullptr, pHid, BT*Nn, HDp, NF, 0);
    gemm_n16_kernel<<<(BT*Nn*16 + 255)/256, 256>>>(pHid, Wds, bds, pDs, BT*Nn);

    // 3) sparse mixing -> Ms (into g_x) + per-token means
    sparse_ms_kernel<<<BT, 256>>>(M);

    // 4) periodicity -> g_per (+ optional output tail)
    period_kernel<<<Bb, 256>>>(out + BTD, write_tail);

    // 5) LN1 + fused QKV
    ln_kernel<<<BT, 256>>>(pX, g1, be1, pXn);
    qkv_kernel<<<dim3(Dd/128, 6, 3), 256>>>(pXn, Wq, bq, Wk, bk, Wv, bv);

    // 6) period-sparse attention
    attn_kernel<<<Bb*HH*Tt, 256>>>();

    // 7) output projection + residual (in-place into g_x)
    sgemm_kernel<<<dim3(Dd/128, 6), 256>>>(pAo, Wo, bo, pX, pX, BT, Dd, Dd, 0);

    // 8) FFN
    ln_kernel<<<BT, 256>>>(pX, g2, be2, pXn);
    sgemm_kernel<<<dim3(DFF/128, 6), 256>>>(pXn, W1, b1, nullptr, pFfn, BT, DFF, Dd, 1);
    sgemm_kernel<<<dim3(Dd/128, 6), 256>>>(pFfn, W2, b2, pX, out, BT, Dd, DFF, 0);
}

// round 12
// speedup vs baseline: 1.1103x; 1.1103x over previous
#include <cuda_runtime.h>
#include <math.h>
#include <stdint.h>

// ---------------- problem constants ----------------
#define Bb   4
#define Tt   168
#define Nn   16
#define Ff   16
#define BT   (Bb*Tt)          // 672
#define Dd   4096
#define HDp  512
#define DFF  16384
#define NF   256              // N*F
#define BTD  (BT*Dd)          // 2752512
#define HH   4                // heads (TOPK)
#define HDIM 1024             // D/H
#define WINC 25
#define PADC 12

// ---------------- scratch (device globals; no allocs) ----------------
__device__ float g_MG[BTD];
__device__ float g_Y[BTD];
__device__ float g_hid[BT*Nn*HDp];
__device__ float g_os[BT*Nn*Nn];
__device__ float g_ds[BT*Nn*Nn];
__device__ float g_x[BTD];
__device__ float g_xn[BTD];
__device__ float g_q[BTD];
__device__ float g_k[BTD];
__device__ float g_v[BTD];
__device__ float g_ao[BTD];
__device__ float g_ffn[BT*DFF];
__device__ float g_xm[BT];
__device__ int   g_per[Bb*HH];
__device__ float g_To[3*Nn*Nn];
__device__ float g_Td[3*Nn*Nn];

// ---------------- Chebyshev basis ----------------
__global__ void basis_kernel(const float* __restrict__ Lo, const float* __restrict__ Ld)
{
    int tid = threadIdx.x;
    int i = tid >> 4, j = tid & 15;
    float eye = (i == j) ? 1.f : 0.f;
    float so = 0.f, sd = 0.f;
    #pragma unroll
    for (int k = 0; k < 16; k++) {
        so = fmaf(Lo[i*16+k], Lo[k*16+j], so);
        sd = fmaf(Ld[i*16+k], Ld[k*16+j], sd);
    }
    g_To[0*256+tid] = eye;
    g_To[1*256+tid] = Lo[tid];
    g_To[2*256+tid] = 2.f*so - eye;
    g_Td[0*256+tid] = eye;
    g_Td[1*256+tid] = Ld[tid];
    g_Td[2*256+tid] = 2.f*sd - eye;
}

// ---------------- TwoDGCN ----------------
__global__ __launch_bounds__(256) void gcn_kernel(const float* __restrict__ M,
                                                  const float* __restrict__ theta)
{
    int bt = blockIdx.x;
    __shared__ float Msm[16][16][16];
    __shared__ float tmp[16][16][16];
    __shared__ float th[3][3][16][16];
    __shared__ float Tos[3][16][16];
    __shared__ float Tds[3][16][16];
    int tid = threadIdx.x;
    const float* Mb = M + (size_t)bt * 4096;
    for (int idx = tid; idx < 4096; idx += 256) ((float*)Msm)[idx] = Mb[idx];
    for (int idx = tid; idx < 2304; idx += 256) ((float*)th)[idx]  = theta[idx];
    for (int idx = tid; idx < 768;  idx += 256) {
        ((float*)Tos)[idx] = g_To[idx];
        ((float*)Tds)[idx] = g_Td[idx];
    }
    int i = tid >> 4, l = tid & 15;
    float acc[16];
    #pragma unroll
    for (int g = 0; g < 16; g++) acc[g] = 0.f;

    for (int a = 0; a < 3; a++) {
        __syncthreads();
        {
            float o[16];
            #pragma unroll
            for (int f = 0; f < 16; f++) o[f] = 0.f;
            #pragma unroll
            for (int j = 0; j < 16; j++) {
                float w = Tos[a][i][j];
                #pragma unroll
                for (int f = 0; f < 16; f++) o[f] = fmaf(w, Msm[j][l][f], o[f]);
            }
            #pragma unroll
            for (int f = 0; f < 16; f++) tmp[i][l][f] = o[f];
        }
        __syncthreads();
        for (int c = 0; c < 3; c++) {
            float P[16];
            #pragma unroll
            for (int f = 0; f < 16; f++) P[f] = 0.f;
            #pragma unroll
            for (int k = 0; k < 16; k++) {
                float w = Tds[c][k][l];
                #pragma unroll
                for (int f = 0; f < 16; f++) P[f] = fmaf(w, tmp[i][k][f], P[f]);
            }
            #pragma unroll
            for (int f = 0; f < 16; f++) {
                float pv = P[f];
                #pragma unroll
                for (int g = 0; g < 16; g++) acc[g] = fmaf(pv, th[a][c][f][g], acc[g]);
            }
        }
    }
    float* out = g_MG + (size_t)bt * 4096 + (i*16 + l) * 16;
    #pragma unroll
    for (int g = 0; g < 16; g++) out[g] = acc[g];
}

// ---------------- destination view ----------------
__global__ void transY_kernel(const float* __restrict__ M)
{
    int bt = blockIdx.x;
    int tid = threadIdx.x;
    int n = tid >> 4, k = tid & 15;
    const float* src = M   + (((size_t)bt*16 + k)*16 + n)*16;
    float*       dst = g_Y + (((size_t)bt*16 + n)*16 + k)*16;
    #pragma unroll
    for (int f = 0; f < 16; f++) dst[f] = src[f];
}

// ---------------- 3xTF32 tensor-core GEMM ----------------
__device__ __forceinline__ float gelu_exact(float v)
{
    return 0.5f * v * (1.0f + erff(v * 0.70710678118654752440f));
}

__device__ __forceinline__ float tf32r(float v)
{
    uint32_t u;
    asm("cvt.rna.tf32.f32 %0, %1;" : "=r"(u) : "f"(v));
    return __uint_as_float(u);
}

__device__ __forceinline__ void tf32split(float v, uint32_t& hi, uint32_t& lo)
{
    float h = tf32r(v);
    hi = __float_as_uint(h);
    lo = __float_as_uint(tf32r(v - h));
}

#define SW 132   // 128 + 4 pad

#define MMA_TF32(acc, a0, a1, a2, a3, b0, b1)                                   \
    asm volatile(                                                               \
        "mma.sync.aligned.m16n8k8.row.col.f32.tf32.tf32.f32 "                   \
        "{%0,%1,%2,%3}, {%4,%5,%6,%7}, {%8,%9}, {%0,%1,%2,%3};"                 \
        : "+f"(acc[0]), "+f"(acc[1]), "+f"(acc[2]), "+f"(acc[3])                \
        : "r"(a0), "r"(a1), "r"(a2), "r"(a3), "r"(b0), "r"(b1))

__global__ __launch_bounds__(256) void tgemm_kernel(
    const float* __restrict__ A, const float* __restrict__ W,
    const float* __restrict__ bias, const float* __restrict__ res,
    float* __restrict__ C, int M, int N, int K, int act)
{
    __shared__ float As[2][16][SW];
    __shared__ float Bs[2][16][SW];

    int tid  = threadIdx.x;
    int warp = tid >> 5;
    int lane = tid & 31;
    int g    = lane >> 2;
    int tg   = lane & 3;
    int wm   = warp & 1;
    int wn   = warp >> 1;
    int bm = blockIdx.y * 128;
    int bn = blockIdx.x * 128;

    int af0 = tid, af1 = tid + 256;
    int ar0 = af0 >> 2, ak0 = (af0 & 3) << 2;
    int ar1 = af1 >> 2, ak1 = (af1 & 3) << 2;
    int bk0 = tid >> 5,         bc0 = (tid & 31) << 2;
    int bk1 = (tid + 256) >> 5, bc1 = bc0;

    float acc[4][4][4];
    #pragma unroll
    for (int mt = 0; mt < 4; mt++)
        #pragma unroll
        for (int nt = 0; nt < 4; nt++)
            #pragma unroll
            for (int r = 0; r < 4; r++) acc[mt][nt][r] = 0.f;

    const float* Arow0 = A + (size_t)(bm + ar0) * K;
    const float* Arow1 = A + (size_t)(bm + ar1) * K;
    bool av0 = (bm + ar0) < M;
    bool av1 = (bm + ar1) < M;

    {
        float4 a0 = av0 ? *(const float4*)(Arow0 + ak0) : make_float4(0,0,0,0);
        float4 a1 = av1 ? *(const float4*)(Arow1 + ak1) : make_float4(0,0,0,0);
        As[0][ak0+0][ar0] = a0.x; As[0][ak0+1][ar0] = a0.y;
        As[0][ak0+2][ar0] = a0.z; As[0][ak0+3][ar0] = a0.w;
        As[0][ak1+0][ar1] = a1.x; As[0][ak1+1][ar1] = a1.y;
        As[0][ak1+2][ar1] = a1.z; As[0][ak1+3][ar1] = a1.w;
        *(float4*)&Bs[0][bk0][bc0] = *(const float4*)(W + (size_t)bk0 * N + bn + bc0);
        *(float4*)&Bs[0][bk1][bc1] = *(const float4*)(W + (size_t)bk1 * N + bn + bc1);
    }
    __syncthreads();

    int nk = K >> 4;
    for (int kt = 0; kt < nk; kt++) {
        int cur = kt & 1;
        bool has_next = (kt + 1) < nk;
        float4 pa0, pa1, pb0, pb1;
        if (has_next) {
            int ko = (kt + 1) << 4;
            pa0 = av0 ? *(const float4*)(Arow0 + ko + ak0) : make_float4(0,0,0,0);
            pa1 = av1 ? *(const float4*)(Arow1 + ko + ak1) : make_float4(0,0,0,0);
            pb0 = *(const float4*)(W + (size_t)(ko + bk0) * N + bn + bc0);
            pb1 = *(const float4*)(W + (size_t)(ko + bk1) * N + bn + bc1);
        }

        #pragma unroll
        for (int kp = 0; kp < 2; kp++) {
            int k0 = kp << 3;
            uint32_t bh[4][2], bl[4][2];
            #pragma unroll
            for (int nt = 0; nt < 4; nt++) {
                int c0 = wn*32 + nt*8 + g;
                tf32split(Bs[cur][k0 + tg    ][c0], bh[nt][0], bl[nt][0]);
                tf32split(Bs[cur][k0 + tg + 4][c0], bh[nt][1], bl[nt][1]);
            }
            #pragma unroll
            for (int mt = 0; mt < 4; mt++) {
                int r0 = wm*64 + mt*16;
                uint32_t ah[4], al[4];
                tf32split(As[cur][k0 + tg    ][r0 + g    ], ah[0], al[0]);
                tf32split(As[cur][k0 + tg    ][r0 + g + 8], ah[1], al[1]);
                tf32split(As[cur][k0 + tg + 4][r0 + g    ], ah[2], al[2]);
                tf32split(As[cur][k0 + tg + 4][r0 + g + 8], ah[3], al[3]);
                #pragma unroll
                for (int nt = 0; nt < 4; nt++) {
                    MMA_TF32(acc[mt][nt], ah[0], ah[1], ah[2], ah[3], bl[nt][0], bl[nt][1]);
                    MMA_TF32(acc[mt][nt], al[0], al[1], al[2], al[3], bh[nt][0], bh[nt][1]);
                    MMA_TF32(acc[mt][nt], ah[0], ah[1], ah[2], ah[3], bh[nt][0], bh[nt][1]);
                }
            }
        }

        if (has_next) {
            int nxt = cur ^ 1;
            As[nxt][ak0+0][ar0] = pa0.x; As[nxt][ak0+1][ar0] = pa0.y;
            As[nxt][ak0+2][ar0] = pa0.z; As[nxt][ak0+3][ar0] = pa0.w;
            As[nxt][ak1+0][ar1] = pa1.x; As[nxt][ak1+1][ar1] = pa1.y;
            As[nxt][ak1+2][ar1] = pa1.z; As[nxt][ak1+3][ar1] = pa1.w;
            *(float4*)&Bs[nxt][bk0][bc0] = pb0;
            *(float4*)&Bs[nxt][bk1][bc1] = pb1;
            __syncthreads();
        }
    }

    #pragma unroll
    for (int mt = 0; mt < 4; mt++) {
        #pragma unroll
        for (int rr = 0; rr < 2; rr++) {
            int row = bm + wm*64 + mt*16 + g + rr*8;
            if (row < M) {
                size_t rbase = (size_t)row * N;
                #pragma unroll
                for (int nt = 0; nt < 4; nt++) {
                    int col = bn + wn*32 + nt*8 + 2*tg;
                    #pragma unroll
                    for (int cc = 0; cc < 2; cc++) {
                        float v = acc[mt][nt][rr*2 + cc];
                        if (bias) v += bias[col + cc];
                        if (act == 1) v = gelu_exact(v);
                        if (res) v += res[rbase + col + cc];
                        C[rbase + col + cc] = v;
                    }
                }
            }
        }
    }
}

// ---------------- small GEMM: (Mrows x 512)@(512 x 16) + bias ----------------
__global__ void gemm_n16_kernel(const float* __restrict__ A, const float* __restrict__ W,
                                const float* __restrict__ bias, float* __restrict__ C, int Mrows)
{
    int g = blockIdx.x * blockDim.x + threadIdx.x;
    if (g >= Mrows * 16) return;
    int row = g >> 4, o = g & 15;
    const float* a = A + (size_t)row * 512;
    float s = 0.f;
    for (int k = 0; k < 512; k++) s = fmaf(a[k], W[k*16 + o], s);
    C[g] = s + bias[o];
}

// ---------------- entropy-sparse OD mixing + Ms + row means ----------------
__global__ __launch_bounds__(256) void sparse_ms_kernel(const float* __restrict__ M)
{
    int bt = blockIdx.x;
    int tid = threadIdx.x;
    __shared__ float Msm[16][16][16];
    __shared__ float tsm[16][16][16];
    __shared__ float po[16][16], pd[16][16];
    __shared__ float ento[16], entd[16];
    __shared__ int   selo[16], seld[16];
    __shared__ float red[256];

    const float* Mb = M + (size_t)bt * 4096;
    for (int idx = tid; idx < 4096; idx += 256) ((float*)Msm)[idx] = Mb[idx];

    if (tid < 32) {
        int r = tid & 15;
        const float* src = (tid < 16 ? g_os : g_ds) + (size_t)bt*256 + r*16;
        float mx = -1e30f;
        #pragma unroll
        for (int j = 0; j < 16; j++) mx = fmaxf(mx, src[j]);
        float e[16], s = 0.f;
        #pragma unroll
        for (int j = 0; j < 16; j++) { e[j] = expf(src[j] - mx); s += e[j]; }
        float inv = 1.f / s, ent = 0.f;
        #pragma unroll
        for (int j = 0; j < 16; j++) {
            float p = e[j] * inv;
            if (tid < 16) po[r][j] = p; else pd[r][j] = p;
            ent -= p * logf(p + 1e-9f);
        }
        if (tid < 16) ento[r] = ent; else entd[r] = ent;
    }
    __syncthreads();
    if (tid < 2) {
        float* ent = (tid == 0) ? ento : entd;
        int*   sel = (tid == 0) ? selo : seld;
        #pragma unroll
        for (int r = 0; r < 16; r++) sel[r] = 0;
        int i1 = 0; float b1 = 1e30f;
        for (int r = 0; r < 16; r++) if (ent[r] < b1) { b1 = ent[r]; i1 = r; }
        int i2 = 0; float b2 = 1e30f;
        for (int r = 0; r < 16; r++) if (r != i1 && ent[r] < b2) { b2 = ent[r]; i2 = r; }
        sel[i1] = 1; sel[i2] = 1;
    }
    __syncthreads();

    {
        int i = tid >> 4, k = tid & 15;
        float o[16];
        #pragma unroll
        for (int f = 0; f < 16; f++) o[f] = 0.f;
        if (selo[i]) {
            #pragma unroll
            for (int j = 0; j < 16; j++) {
                float w = po[i][j];
                #pragma unroll
                for (int f = 0; f < 16; f++) o[f] = fmaf(w, Msm[j][k][f], o[f]);
            }
        }
        #pragma unroll
        for (int f = 0; f < 16; f++) tsm[i][k][f] = o[f];
    }
    __syncthreads();

    int ii = tid >> 4, jj = tid & 15;
    float dj[16];
    #pragma unroll
    for (int f = 0; f < 16; f++) dj[f] = seld[jj] ? pd[jj][f] : 0.f;
    const float* MGb = g_MG + (size_t)bt * 4096;
    float*       xb  = g_x  + (size_t)bt * 4096;
    float local = 0.f;
    #pragma unroll
    for (int kk = 0; kk < 16; kk++) {
        float ma = 0.f;
        #pragma unroll
        for (int f = 0; f < 16; f++) ma = fmaf(tsm[ii][kk][f], dj[f], ma);
        int idx = (ii*16 + jj)*16 + kk;
        float ms = 0.5f * (MGb[idx] + ma);
        xb[idx] = ms;
        local += ms;
    }
    red[tid] = local;
    __syncthreads();
    for (int off = 128; off > 0; off >>= 1) {
        if (tid < off) red[tid] += red[tid + off];
        __syncthreads();
    }
    if (tid == 0) g_xm[bt] = red[0] / 4096.f;
}

// ---------------- periodicity ----------------
__global__ void period_kernel(float* __restrict__ out_tail, int write_tail)
{
    int b = blockIdx.x;
    int tid = threadIdx.x;
    __shared__ float xs[Tt], det[Tt], xc[Tt], ac[Tt];
    __shared__ float red[256];
    if (tid < Tt) xs[tid] = g_xm[b*Tt + tid];
    __syncthreads();
    if (tid < Tt) {
        float s = 0.f;
        for (int d = -PADC; d <= PADC; d++) {
            int u = tid + d;
            u = u < 0 ? 0 : (u > Tt-1 ? Tt-1 : u);
            s += xs[u];
        }
        det[tid] = xs[tid] - s / (float)WINC;
    }
    __syncthreads();
    red[tid] = (tid < Tt) ? det[tid] : 0.f;
    __syncthreads();
    for (int off = 128; off > 0; off >>= 1) {
        if (tid < off) red[tid] += red[tid + off];
        __syncthreads();
    }
    float mean = red[0] / (float)Tt;
    if (tid < Tt) xc[tid] = det[tid] - mean;
    __syncthreads();
    if (tid < Tt) {
        int k = tid;
        float s = 0.f;
        for (int u = 0; u + k < Tt; u++) s = fmaf(xc[u], xc[u+k], s);
        ac[k] = (k < 2) ? -1e9f : s;
    }
    __syncthreads();
    if (tid == 0) {
        int used[HH];
        for (int r = 0; r < HH; r++) {
            float best = -1e30f; int bi = 0;
            for (int k = 0; k < Tt; k++) {
                bool skip = false;
                for (int q = 0; q < r; q++) if (used[q] == k) skip = true;
                if (!skip && ac[k] > best) { best = ac[k]; bi = k; }
            }
            used[r] = bi;
            g_per[b*HH + r] = bi;
            if (write_tail) out_tail[b*HH + r] = (float)bi;
        }
    }
}

// ---------------- LayerNorm ----------------
__global__ __launch_bounds__(256) void ln_kernel(const float* __restrict__ X,
                                                 const float* __restrict__ gam,
                                                 const float* __restrict__ bet,
                                                 float* __restrict__ Y)
{
    int row = blockIdx.x;
    int tid = threadIdx.x;
    __shared__ float red[256];
    __shared__ float mu_s, rs_s;
    const float* x = X + (size_t)row * Dd;
    float s = 0.f;
    for (int i = tid; i < Dd; i += 256) s += x[i];
    red[tid] = s; __syncthreads();
    for (int off = 128; off > 0; off >>= 1) {
        if (tid < off) red[tid] += red[tid + off];
        __syncthreads();
    }
    if (tid == 0) mu_s = red[0] / (float)Dd;
    __syncthreads();
    float mu = mu_s;
    float s2 = 0.f;
    for (int i = tid; i < Dd; i += 256) { float d = x[i] - mu; s2 = fmaf(d, d, s2); }
    red[tid] = s2; __syncthreads();
    for (int off = 128; off > 0; off >>= 1) {
        if (tid < off) red[tid] += red[tid + off];
        __syncthreads();
    }
    if (tid == 0) rs_s = rsqrtf(red[0] / (float)Dd + 1e-5f);
    __syncthreads();
    float rs = rs_s;
    float* y = Y + (size_t)row * Dd;
    for (int i = tid; i < Dd; i += 256)
        y[i] = (x[i] - mu) * rs * gam[i] + bet[i];
}

// ---------------- period-sparse causal attention ----------------
__global__ __launch_bounds__(256) void attn_kernel()
{
    int blk = blockIdx.x;
    int i = blk % Tt;
    int h = (blk / Tt) & 3;
    int b = blk / (Tt * HH);
    int p = g_per[b*HH + h];
    if (p < 1) p = 1;
    int nj = i / p + 1;

    __shared__ float sc[96];
    __shared__ float sinv;
    int tid = threadIdx.x, lane = tid & 31, w = tid >> 5;

    const float* q = g_q + ((size_t)(b*Tt + i) * Dd) + h*HDIM;
    for (int m = w; m < nj; m += 8) {
        int j = i - m*p;
        const float* kr = g_k + ((size_t)(b*Tt + j) * Dd) + h*HDIM;
        float s = 0.f;
        for (int l = lane; l < HDIM; l += 32) s = fmaf(q[l], kr[l], s);
        #pragma unroll
        for (int off = 16; off; off >>= 1) s += __shfl_xor_sync(0xffffffffu, s, off);
        if (lane == 0) sc[m] = s * (1.f/32.f);
    }
    __syncthreads();
    if (tid == 0) {
        float mx = -1e30f;
        for (int m = 0; m < nj; m++) mx = fmaxf(mx, sc[m]);
        float su = 0.f;
        for (int m = 0; m < nj; m++) { float e = expf(sc[m] - mx); sc[m] = e; su += e; }
        sinv = 1.f / su;
    }
    __syncthreads();
    float inv = sinv;
    float acc[4] = {0.f, 0.f, 0.f, 0.f};
    for (int m = 0; m < nj; m++) {
        int j = i - m*p;
        float a = sc[m] * inv;
        const float* vr = g_v + ((size_t)(b*Tt + j) * Dd) + h*HDIM;
        #pragma unroll
        for (int u = 0; u < 4; u++) acc[u] = fmaf(a, vr[tid + u*256], acc[u]);
    }
    float* o = g_ao + ((size_t)(b*Tt + i) * Dd) + h*HDIM;
    #pragma unroll
    for (int u = 0; u < 4; u++) o[tid + u*256] = acc[u];
}

// ---------------- launch ----------------
extern "C" void kernel_launch(void* const* d_in, const int* in_sizes, int n_in,
                              void* d_out, int out_size)
{
    const float* M     = (const float*)d_in[0];
    const float* L_o   = (const float*)d_in[1];
    const float* L_d   = (const float*)d_in[2];
    const float* theta = (const float*)d_in[3];
    const float* Wop   = (const float*)d_in[4];
    const float* bop   = (const float*)d_in[5];
    const float* Wdp   = (const float*)d_in[6];
    const float* bdp   = (const float*)d_in[7];
    const float* Wos   = (const float*)d_in[8];
    const float* bos   = (const float*)d_in[9];
    const float* Wds   = (const float*)d_in[10];
    const float* bds   = (const float*)d_in[11];
    const float* Wq    = (const float*)d_in[12];
    const float* bq    = (const float*)d_in[13];
    const float* Wk    = (const float*)d_in[14];
    const float* bk    = (const float*)d_in[15];
    const float* Wv    = (const float*)d_in[16];
    const float* bv    = (const float*)d_in[17];
    const float* Wo    = (const float*)d_in[18];
    const float* bo    = (const float*)d_in[19];
    const float* W1    = (const float*)d_in[20];
    const float* b1    = (const float*)d_in[21];
    const float* W2    = (const float*)d_in[22];
    const float* b2    = (const float*)d_in[23];
    const float* g1    = (const float*)d_in[24];
    const float* be1   = (const float*)d_in[25];
    const float* g2    = (const float*)d_in[26];
    const float* be2   = (const float*)d_in[27];

    float *pY, *pHid, *pOs, *pDs, *pX, *pXn, *pQ, *pK, *pV, *pAo, *pFfn;
    cudaGetSymbolAddress((void**)&pY,   g_Y);
    cudaGetSymbolAddress((void**)&pHid, g_hid);
    cudaGetSymbolAddress((void**)&pOs,  g_os);
    cudaGetSymbolAddress((void**)&pDs,  g_ds);
    cudaGetSymbolAddress((void**)&pX,   g_x);
    cudaGetSymbolAddress((void**)&pXn,  g_xn);
    cudaGetSymbolAddress((void**)&pQ,   g_q);
    cudaGetSymbolAddress((void**)&pK,   g_k);
    cudaGetSymbolAddress((void**)&pV,   g_v);
    cudaGetSymbolAddress((void**)&pAo,  g_ao);
    cudaGetSymbolAddress((void**)&pFfn, g_ffn);

    float* out = (float*)d_out;
    int write_tail = (out_size >= BTD + Bb*HH) ? 1 : 0;

    // 1) GCN branch
    basis_kernel<<<1, 256>>>(L_o, L_d);
    gcn_kernel<<<BT, 256>>>(M, theta);

    // 2) OD attention scores (3xTF32 tensor GEMMs)
    transY_kernel<<<BT, 256>>>(M);
    tgemm_kernel<<<dim3(HDp/128, (BT*Nn)/128), 256>>>(M,  Wop, bop, nullptr, pHid, BT*Nn, HDp, NF, 0);
    gemm_n16_kernel<<<(BT*Nn*16 + 255)/256, 256>>>(pHid, Wos, bos, pOs, BT*Nn);
    tgemm_kernel<<<dim3(HDp/128, (BT*Nn)/128), 256>>>(pY, Wdp, bdp, nullptr, pHid, BT*Nn, HDp, NF, 0);
    gemm_n16_kernel<<<(BT*Nn*16 + 255)/256, 256>>>(pHid, Wds, bds, pDs, BT*Nn);

    // 3) sparse mixing -> Ms (into g_x) + per-token means
    sparse_ms_kernel<<<BT, 256>>>(M);

    // 4) periodicity -> g_per (+ optional output tail)
    period_kernel<<<Bb, 256>>>(out + BTD, write_tail);

    // 5) LN1 + QKV (3xTF32)
    ln_kernel<<<BT, 256>>>(pX, g1, be1, pXn);
    tgemm_kernel<<<dim3(Dd/128, 6), 256>>>(pXn, Wq, bq, nullptr, pQ, BT, Dd, Dd, 0);
    tgemm_kernel<<<dim3(Dd/128, 6), 256>>>(pXn, Wk, bk, nullptr, pK, BT, Dd, Dd, 0);
    tgemm_kernel<<<dim3(Dd/128, 6), 256>>>(pXn, Wv, bv, nullptr, pV, BT, Dd, Dd, 0);

    // 6) period-sparse attention
    attn_kernel<<<Bb*HH*Tt, 256>>>();

    // 7) output projection + residual (3xTF32, in-place into g_x)
    tgemm_kernel<<<dim3(Dd/128, 6), 256>>>(pAo, Wo, bo, pX, pX, BT, Dd, Dd, 0);

    // 8) FFN (3xTF32)
    ln_kernel<<<BT, 256>>>(pX, g2, be2, pXn);
    tgemm_kernel<<<dim3(DFF/128, 6), 256>>>(pXn, W1, b1, nullptr, pFfn, BT, DFF, Dd, 1);
    tgemm_kernel<<<dim3(Dd/128, 6), 256>>>(pFfn, W2, b2, pX, out, BT, Dd, DFF, 0);
}